// round 15
// baseline (speedup 1.0000x reference)
#include <cuda_runtime.h>
#include <cuda_bf16.h>
#include <math.h>

#define Bq 256
#define Tq 512
#define Iq 12
#define Hq 1024
#define Zq 128
#define G3 3072
#define NBLK 128
#define NTHR 512
#define NWARP 2048
#define OFF_MEAN (Bq*Tq*Iq)
#define OFF_STD  (OFF_MEAN + Bq*Zq)

__device__ float g_hf[2][Bq*Hq];
__device__ float g_hb[2][Bq*Hq];
__device__ float g_hd[2][Bq*Hq];
__device__ float g_z[Bq*Zq];
__device__ float g_giz[Bq*G3];
__device__ unsigned g_cnt = 0;
__device__ unsigned g_gen = 0;

struct Smem {
    uint4 ASH[8*2*32], ASL[8*2*32];       // A frags hi/lo: [mt][kk][lane]
    uint2 WSH[3*4*2*32], WSL[3*4*2*32];   // W frags hi/lo: [g][nt][kk][lane]
    float Xs[128*Iq], Wis[96*Iq];
};

__device__ __forceinline__ unsigned pkbf(float lo, float hi){
    unsigned r; asm("cvt.rn.bf16x2.f32 %0, %1, %2;":"=r"(r):"f"(hi),"f"(lo)); return r;
}
__device__ __forceinline__ float bres(float v){
    return v - __bfloat162float(__float2bfloat16(v));
}
__device__ __forceinline__ void mmab(float* c, const uint4 a, unsigned b0, unsigned b1){
    asm volatile("mma.sync.aligned.m16n8k16.row.col.f32.bf16.bf16.f32 "
        "{%0,%1,%2,%3},{%4,%5,%6,%7},{%8,%9},{%0,%1,%2,%3};"
        : "+f"(c[0]),"+f"(c[1]),"+f"(c[2]),"+f"(c[3])
        : "r"(a.x),"r"(a.y),"r"(a.z),"r"(a.w),"r"(b0),"r"(b1));
}
__device__ __forceinline__ float sgm(float v){ return 1.f/(1.f + expf(-v)); }
__device__ __forceinline__ float wred(float v){
    #pragma unroll
    for (int o = 16; o > 0; o >>= 1) v += __shfl_down_sync(0xffffffffu, v, o);
    return v;
}
__device__ __forceinline__ void gbar(){
    __syncthreads();
    if (threadIdx.x == 0){
        unsigned my = *(volatile unsigned*)&g_gen;
        __threadfence();
        if (atomicAdd(&g_cnt, 1u) == NBLK - 1u){
            atomicExch(&g_cnt, 0u); __threadfence(); atomicAdd(&g_gen, 1u);
        } else {
            while (*(volatile unsigned*)&g_gen == my) __nanosleep(32);
            __threadfence();
        }
    }
    __syncthreads();
}

template<int DEC>
__device__ __forceinline__ void emit(float sr, float sz, float sn, float gx,
    int m, int j, float br, float bz, float bn, float cr, float cz, float cn,
    const float* __restrict__ hold, float* __restrict__ hnew)
{
    float gr = br, gz = bz, gn = bn;
    if (DEC){
        gr = __ldcg(&g_giz[m*G3 + j]);
        gz = __ldcg(&g_giz[m*G3 + Hq + j]);
        gn = __ldcg(&g_giz[m*G3 + 2*Hq + j]);
    }
    float rr = sgm(sr + gr + cr);
    float zz = sgm(sz + gz + cz);
    float nn = tanhf(gx + gn + rr*(sn + cn));
    float ho = __ldcg(&hold[m*Hq + j]);
    hnew[m*Hq + j] = (1.f - zz)*nn + zz*ho;
}

// BMT m16-tiles per block (8 enc / 4 dec), BN=32. Split-bf16 HMMA over K=1024.
template<int BMT, int DEC>
__device__ __forceinline__ void gtile(Smem* sm,
    const float* __restrict__ x, int tt,
    const float* __restrict__ Wih, int ihs,
    const float* __restrict__ Whh,
    const float* __restrict__ bih, const float* __restrict__ bhh,
    const float* __restrict__ hold, float* __restrict__ hnew,
    int m0, int n0)
{
    const int NTI = BMT/4;
    const int tid = threadIdx.x, l = tid & 31, w = tid >> 5;
    const int nq = w & 3, mw = w >> 2;

    __syncthreads();
    for (int idx = tid; idx < BMT*16*Iq; idx += NTHR){
        int r = idx/Iq, c = idx - r*Iq;
        float v;
        if (DEC && tt == 0) v = (c == Iq-1) ? 1.f : 0.f;
        else v = __ldg(&x[(m0 + r)*(Tq*Iq) + (DEC ? tt-1 : tt)*Iq + c]);
        sm->Xs[r*Iq + c] = v;
    }
    for (int idx = tid; idx < 96*Iq; idx += NTHR){
        int n = idx/Iq, c = idx - n*Iq;
        sm->Wis[idx] = __ldg(&Wih[((n>>5)*Hq + n0 + (n&31))*ihs + c]);
    }

    float ar[NTI][4], az[NTI][4], an[NTI][4];
    #pragma unroll
    for (int t2 = 0; t2 < NTI; t2++)
        #pragma unroll
        for (int i = 0; i < 4; i++){ ar[t2][i]=0.f; az[t2][i]=0.f; an[t2][i]=0.f; }

    #pragma unroll 1
    for (int kb = 0; kb < 32; kb++){
        const int k0 = kb*32;
        __syncthreads();
        for (int idx = tid; idx < BMT*64; idx += NTHR){
            int mt = idx>>6, kk = (idx>>5)&1, li = idx&31;
            int row = m0 + mt*16 + (li>>2), col = k0 + kk*16 + 2*(li&3);
            float2 v00 = __ldcg((const float2*)&hold[row*Hq + col]);
            float2 v10 = __ldcg((const float2*)&hold[(row+8)*Hq + col]);
            float2 v01 = __ldcg((const float2*)&hold[row*Hq + col + 8]);
            float2 v11 = __ldcg((const float2*)&hold[(row+8)*Hq + col + 8]);
            int o = (mt*2 + kk)*32 + li;
            sm->ASH[o] = make_uint4(pkbf(v00.x,v00.y), pkbf(v10.x,v10.y),
                                    pkbf(v01.x,v01.y), pkbf(v11.x,v11.y));
            sm->ASL[o] = make_uint4(pkbf(bres(v00.x),bres(v00.y)), pkbf(bres(v10.x),bres(v10.y)),
                                    pkbf(bres(v01.x),bres(v01.y)), pkbf(bres(v11.x),bres(v11.y)));
        }
        for (int idx = tid; idx < 768; idx += NTHR){
            int g = idx>>8, rem = idx&255, nt = rem>>6, kk = (rem>>5)&1, li = rem&31;
            int wrow = (g*Hq + n0 + nt*8 + (li>>2))*Hq + k0 + kk*16 + 2*(li&3);
            float2 w0 = __ldg((const float2*)&Whh[wrow]);
            float2 w1 = __ldg((const float2*)&Whh[wrow + 8]);
            int o = ((g*4 + nt)*2 + kk)*32 + li;
            sm->WSH[o] = make_uint2(pkbf(w0.x,w0.y), pkbf(w1.x,w1.y));
            sm->WSL[o] = make_uint2(pkbf(bres(w0.x),bres(w0.y)), pkbf(bres(w1.x),bres(w1.y)));
        }
        __syncthreads();
        #pragma unroll
        for (int kk = 0; kk < 2; kk++){
            uint2 wh0 = sm->WSH[((0*4+nq)*2+kk)*32 + l], wl0 = sm->WSL[((0*4+nq)*2+kk)*32 + l];
            uint2 wh1 = sm->WSH[((1*4+nq)*2+kk)*32 + l], wl1 = sm->WSL[((1*4+nq)*2+kk)*32 + l];
            uint2 wh2 = sm->WSH[((2*4+nq)*2+kk)*32 + l], wl2 = sm->WSL[((2*4+nq)*2+kk)*32 + l];
            #pragma unroll
            for (int ti = 0; ti < NTI; ti++){
                int mt = (NTI==2) ? mw*2 + ti : mw;
                uint4 ah = sm->ASH[(mt*2+kk)*32 + l];
                uint4 al = sm->ASL[(mt*2+kk)*32 + l];
                mmab(ar[ti], ah, wh0.x, wh0.y);
                mmab(ar[ti], ah, wl0.x, wl0.y);
                mmab(ar[ti], al, wh0.x, wh0.y);
                mmab(az[ti], ah, wh1.x, wh1.y);
                mmab(az[ti], ah, wl1.x, wl1.y);
                mmab(az[ti], al, wh1.x, wh1.y);
                mmab(an[ti], ah, wh2.x, wh2.y);
                mmab(an[ti], ah, wl2.x, wl2.y);
                mmab(an[ti], al, wh2.x, wh2.y);
            }
        }
    }

    const int jl0 = nq*8 + 2*(l&3);
    #pragma unroll
    for (int ti = 0; ti < NTI; ti++){
        int mt = (NTI==2) ? mw*2 + ti : mw;
        #pragma unroll
        for (int rs = 0; rs < 2; rs++){
            int m = m0 + mt*16 + (l>>2) + 8*rs;
            #pragma unroll
            for (int jc = 0; jc < 2; jc++){
                int jl = jl0 + jc, j = n0 + jl, c = rs*2 + jc;
                float xr = 0.f, xz = 0.f, xn = 0.f;
                #pragma unroll
                for (int cc = 0; cc < Iq; cc++){
                    float xv = sm->Xs[(m - m0)*Iq + cc];
                    xr += xv*sm->Wis[jl*Iq + cc];
                    xz += xv*sm->Wis[(32 + jl)*Iq + cc];
                    xn += xv*sm->Wis[(64 + jl)*Iq + cc];
                }
                float br = 0.f, bz = 0.f, bn = 0.f;
                if (!DEC){ br = __ldg(&bih[j]); bz = __ldg(&bih[Hq+j]); bn = __ldg(&bih[2*Hq+j]); }
                emit<DEC>(ar[ti][c] + xr, az[ti][c] + xz, an[ti][c], xn, m, j,
                          br, bz, bn,
                          __ldg(&bhh[j]), __ldg(&bhh[Hq+j]), __ldg(&bhh[2*Hq+j]),
                          hold, hnew);
            }
        }
    }
}

__global__ void __launch_bounds__(NTHR, 1) vae_kernel(
    const float* __restrict__ x, const float* __restrict__ noise,
    const float* __restrict__ Wih_f, const float* __restrict__ Whh_f,
    const float* __restrict__ bih_f, const float* __restrict__ bhh_f,
    const float* __restrict__ Wih_b, const float* __restrict__ Whh_b,
    const float* __restrict__ bih_b, const float* __restrict__ bhh_b,
    const float* __restrict__ Wmu,  const float* __restrict__ bmu,
    const float* __restrict__ Wvar, const float* __restrict__ bvar,
    const float* __restrict__ Winit,const float* __restrict__ binit,
    const float* __restrict__ Wout, const float* __restrict__ bout,
    const float* __restrict__ Wcih, const float* __restrict__ Wchh,
    const float* __restrict__ bcih, const float* __restrict__ bchh,
    float* __restrict__ out)
{
    __shared__ Smem sm;
    const int blk = blockIdx.x, tid = threadIdx.x;
    const int lane = tid & 31;
    const int gwp = blk*16 + (tid >> 5);

    for (int i = blk*NTHR + tid; i < Bq*Hq; i += NBLK*NTHR){
        g_hf[0][i] = 0.f; g_hb[0][i] = 0.f;
    }
    gbar();

    const int edir = blk >> 6, erem = blk & 63;
    const int em0 = (erem >> 5)*128, en0 = (erem & 31)*32;
    for (int t = 0; t < Tq; t++){
        int par = t & 1;
        if (edir == 0)
            gtile<8,0>(&sm, x, t, Wih_f, Iq, Whh_f, bih_f, bhh_f,
                       g_hf[par], g_hf[par^1], em0, en0);
        else
            gtile<8,0>(&sm, x, Tq-1-t, Wih_b, Iq, Whh_b, bih_b, bhh_b,
                       g_hb[par], g_hb[par^1], em0, en0);
        gbar();
    }

    for (int it = gwp; it < Bq*Zq; it += NWARP){
        int m = it >> 7, zi = it & 127;
        const float* hf = &g_hf[0][m*Hq];
        const float* hb = &g_hb[0][m*Hq];
        const float* wm = &Wmu[zi*2*Hq];
        const float* wv = &Wvar[zi*2*Hq];
        float am = 0.f, av = 0.f;
        for (int k = lane; k < Hq; k += 32){
            float h1 = __ldcg(&hf[k]); am += h1*__ldg(&wm[k]);    av += h1*__ldg(&wv[k]);
            float h2 = __ldcg(&hb[k]); am += h2*__ldg(&wm[Hq+k]); av += h2*__ldg(&wv[Hq+k]);
        }
        am = wred(am); av = wred(av);
        if (lane == 0){
            float mean = am + __ldg(&bmu[zi]);
            float sd = expf(0.5f*(av + __ldg(&bvar[zi])));
            out[OFF_MEAN + m*Zq + zi] = mean;
            out[OFF_STD  + m*Zq + zi] = sd;
            g_z[m*Zq + zi] = mean + sd*__ldg(&noise[m*Zq + zi]);
        }
    }
    gbar();

    for (int it = gwp; it < Bq*G3; it += NWARP){
        int m = it / G3, gc = it - m*G3;
        const float* zr = &g_z[m*Zq];
        const float* wr = &Wcih[gc*(Iq + Zq) + Iq];
        float acc = 0.f;
        for (int k = lane; k < Zq; k += 32) acc += __ldcg(&zr[k])*__ldg(&wr[k]);
        acc = wred(acc);
        if (lane == 0) g_giz[m*G3 + gc] = acc + __ldg(&bcih[gc]);
    }
    for (int it = gwp; it < Bq*Hq; it += NWARP){
        int m = it >> 10, jj = it & 1023;
        const float* zr = &g_z[m*Zq];
        const float* wr = &Winit[jj*Zq];
        float acc = 0.f;
        for (int k = lane; k < Zq; k += 32) acc += __ldcg(&zr[k])*__ldg(&wr[k]);
        acc = wred(acc);
        if (lane == 0) g_hd[0][m*Hq + jj] = tanhf(acc + __ldg(&binit[jj]));
    }
    gbar();

    const int dm0 = (blk >> 5)*64, dn0 = (blk & 31)*32;
    for (int t = 0; t < Tq; t++){
        int par = t & 1;
        if (t > 0){
            const float* hbuf = g_hd[par];
            for (int it = gwp; it < Bq*Iq; it += NWARP){
                int m = it / Iq, i = it - m*Iq;
                const float* h = &hbuf[m*Hq];
                const float* ww = &Wout[i*Hq];
                float acc = 0.f;
                for (int k = lane; k < Hq; k += 32) acc += __ldcg(&h[k])*__ldg(&ww[k]);
                acc = wred(acc);
                if (lane == 0)
                    out[m*(Tq*Iq) + (t-1)*Iq + i] = sgm(acc + __ldg(&bout[i]));
            }
        }
        gtile<4,1>(&sm, x, t, Wcih, Iq + Zq, Wchh, bcih, bchh,
                   g_hd[par], g_hd[par^1], dm0, dn0);
        gbar();
    }

    {
        const float* hbuf = g_hd[0];
        for (int it = gwp; it < Bq*Iq; it += NWARP){
            int m = it / Iq, i = it - m*Iq;
            const float* h = &hbuf[m*Hq];
            const float* ww = &Wout[i*Hq];
            float acc = 0.f;
            for (int k = lane; k < Hq; k += 32) acc += __ldcg(&h[k])*__ldg(&ww[k]);
            acc = wred(acc);
            if (lane == 0)
                out[m*(Tq*Iq) + (Tq-1)*Iq + i] = sgm(acc + __ldg(&bout[i]));
        }
    }
}

extern "C" void kernel_launch(void* const* d_in, const int* in_sizes, int n_in,
                              void* d_out, int out_size)
{
    vae_kernel<<<NBLK, NTHR>>>(
        (const float*)d_in[0],  (const float*)d_in[1],
        (const float*)d_in[2],  (const float*)d_in[3],
        (const float*)d_in[4],  (const float*)d_in[5],
        (const float*)d_in[6],  (const float*)d_in[7],
        (const float*)d_in[8],  (const float*)d_in[9],
        (const float*)d_in[10], (const float*)d_in[11],
        (const float*)d_in[12], (const float*)d_in[13],
        (const float*)d_in[14], (const float*)d_in[15],
        (const float*)d_in[16], (const float*)d_in[17],
        (const float*)d_in[18], (const float*)d_in[19],
        (const float*)d_in[20], (const float*)d_in[21],
        (float*)d_out);
}

// round 16
// speedup vs baseline: 1.4893x; 1.4893x over previous
#include <cuda_runtime.h>
#include <cuda_bf16.h>
#include <math.h>
#define Bq 256
#define Tq 512
#define Iq 12
#define Hq 1024
#define Zq 128
#define G3 3072
#define NBLK 128
#define NTHR 512
#define NWARP 2048
#define OFF_MEAN (Bq*Tq*Iq)
#define OFF_STD (OFF_MEAN+Bq*Zq)
#define STG 28672
#define XSo 57344
#define WISo 63488
#define SMTOT 68096
#define AFI(p,ch,kg,mg,l) ((((((p)*3+(ch))*64+(kg))*16+(mg))*32)+(l))
#define WFI(ch,kg,g,ng,l) ((((((ch)*64+(kg))*3+(g))*128+(ng))*32)+(l))

__device__ float g_hf[2][Bq*Hq];
__device__ float g_hb[2][Bq*Hq];
__device__ float g_hd[2][Bq*Hq];
__device__ float g_z[Bq*Zq];
__device__ float g_giz[Bq*G3];
__device__ uint4 g_Afh[2*3*64*16*32];
__device__ uint4 g_Afl[2*3*64*16*32];
__device__ uint4 g_Wfr[3*64*3*128*32];
__device__ unsigned g_cnt = 0, g_gen = 0;

__device__ __forceinline__ unsigned pkbf(float lo, float hi){
    unsigned r; asm("cvt.rn.bf16x2.f32 %0, %1, %2;":"=r"(r):"f"(hi),"f"(lo)); return r;
}
__device__ __forceinline__ float bres(float v){
    return v - __bfloat162float(__float2bfloat16(v));
}
__device__ __forceinline__ void mmab(float* c, const uint4 a, unsigned b0, unsigned b1){
    asm volatile("mma.sync.aligned.m16n8k16.row.col.f32.bf16.bf16.f32 "
        "{%0,%1,%2,%3},{%4,%5,%6,%7},{%8,%9},{%0,%1,%2,%3};"
        : "+f"(c[0]),"+f"(c[1]),"+f"(c[2]),"+f"(c[3])
        : "r"(a.x),"r"(a.y),"r"(a.z),"r"(a.w),"r"(b0),"r"(b1));
}
__device__ __forceinline__ float sgm(float v){ return 1.f/(1.f+expf(-v)); }
__device__ __forceinline__ float wred(float v){
    #pragma unroll
    for (int o=16;o>0;o>>=1) v += __shfl_down_sync(0xffffffffu,v,o);
    return v;
}
__device__ __forceinline__ void gbar(){
    __syncthreads();
    if (threadIdx.x == 0){
        unsigned my = *(volatile unsigned*)&g_gen;
        __threadfence();
        if (atomicAdd(&g_cnt,1u) == NBLK-1u){
            atomicExch(&g_cnt,0u); __threadfence(); atomicAdd(&g_gen,1u);
        } else {
            while (*(volatile unsigned*)&g_gen == my) __nanosleep(32);
            __threadfence();
        }
    }
    __syncthreads();
}

template<int NITA>
__device__ __forceinline__ void stg_cp(unsigned smu, int st, int kb, int par, int ch,
                                       int mtg0, int n0){
    const int tid = threadIdx.x;
    for (int idx = tid; idx < 2*NITA + 768; idx += NTHR){
        const uint4* s; unsigned d; int cg = 1;
        if (idx < NITA){
            int mtl = idx>>6, kk = (idx>>5)&1, li = idx&31;
            s = &g_Afh[AFI(par,ch,kb*2+kk,mtg0+mtl,li)]; d = smu + st*STG + idx*16;
        } else if (idx < 2*NITA){
            int i2 = idx - NITA; int mtl = i2>>6, kk = (i2>>5)&1, li = i2&31;
            s = &g_Afl[AFI(par,ch,kb*2+kk,mtg0+mtl,li)]; d = smu + st*STG + 8192 + i2*16;
        } else {
            int i2 = idx - 2*NITA; int g = i2>>8, nt = (i2>>6)&3, kk = (i2>>5)&1, li = i2&31;
            s = &g_Wfr[WFI(ch,kb*2+kk,g,(n0>>3)+nt,li)]; d = smu + st*STG + 16384 + i2*16;
            cg = 0;
        }
        if (cg) asm volatile("cp.async.cg.shared.global [%0],[%1],16;"::"r"(d),"l"(s):"memory");
        else    asm volatile("cp.async.ca.shared.global [%0],[%1],16;"::"r"(d),"l"(s):"memory");
    }
    asm volatile("cp.async.commit_group;":::"memory");
}

template<int BMT, int DEC>
__device__ __forceinline__ void gtile(char* smc, unsigned smu, int par, int ch,
    const float* __restrict__ x, int tt,
    const float* __restrict__ Wih, int ihs,
    const float* __restrict__ bih, const float* __restrict__ bhh,
    const float* __restrict__ hold, float* __restrict__ hnew, int m0, int n0)
{
    const int NTI = BMT/4, NITA = BMT*64;
    const int tid = threadIdx.x, l = tid&31, w = tid>>5;
    const int nq = w&3, mw = w>>2, mtg0 = m0>>4;
    float* Xs = (float*)(smc + XSo);
    float* Wis = (float*)(smc + WISo);

    stg_cp<NITA>(smu, 0, 0, par, ch, mtg0, n0);
    for (int idx = tid; idx < BMT*16*Iq; idx += NTHR){
        int r = idx/Iq, c = idx - r*Iq; float v;
        if (DEC && tt == 0) v = (c == Iq-1) ? 1.f : 0.f;
        else v = __ldg(&x[(m0+r)*(Tq*Iq) + (DEC?tt-1:tt)*Iq + c]);
        Xs[idx] = v;
    }
    for (int idx = tid; idx < 96*Iq; idx += NTHR){
        int n = idx/Iq, c = idx - n*Iq;
        Wis[idx] = __ldg(&Wih[((n>>5)*Hq + n0 + (n&31))*ihs + c]);
    }

    float ar[NTI][4], az[NTI][4], an[NTI][4];
    #pragma unroll
    for (int t2 = 0; t2 < NTI; t2++)
        #pragma unroll
        for (int i = 0; i < 4; i++){ ar[t2][i]=0.f; az[t2][i]=0.f; an[t2][i]=0.f; }

    #pragma unroll 1
    for (int kb = 0; kb < 32; kb++){
        int st = kb & 1;
        asm volatile("cp.async.wait_group 0;":::"memory");
        __syncthreads();
        if (kb < 31) stg_cp<NITA>(smu, st^1, kb+1, par, ch, mtg0, n0);
        const uint4* ASH = (const uint4*)(smc + st*STG);
        const uint4* ASL = ASH + 512;
        const uint4* WS  = (const uint4*)(smc + st*STG + 16384);
        #pragma unroll
        for (int kk = 0; kk < 2; kk++){
            uint4 w0 = WS[((nq)*2+kk)*32 + l];
            uint4 w1 = WS[((4+nq)*2+kk)*32 + l];
            uint4 w2 = WS[((8+nq)*2+kk)*32 + l];
            #pragma unroll
            for (int ti = 0; ti < NTI; ti++){
                int mt = (NTI==2) ? mw*2+ti : mw;
                uint4 ah = ASH[(mt*2+kk)*32 + l];
                uint4 al = ASL[(mt*2+kk)*32 + l];
                mmab(ar[ti], ah, w0.x, w0.y); mmab(ar[ti], ah, w0.z, w0.w); mmab(ar[ti], al, w0.x, w0.y);
                mmab(az[ti], ah, w1.x, w1.y); mmab(az[ti], ah, w1.z, w1.w); mmab(az[ti], al, w1.x, w1.y);
                mmab(an[ti], ah, w2.x, w2.y); mmab(an[ti], ah, w2.z, w2.w); mmab(an[ti], al, w2.x, w2.y);
            }
        }
    }

    const int jl0 = nq*8 + 2*(l&3), kkj = (n0 + nq*8) >> 4, sl0 = 2*(nq&1);
    #pragma unroll
    for (int ti = 0; ti < NTI; ti++){
        int mt = (NTI==2) ? mw*2+ti : mw; int mtg = mtg0 + mt;
        #pragma unroll
        for (int rs = 0; rs < 2; rs++){
            int m = m0 + mt*16 + (l>>2) + 8*rs;
            float hv[2];
            #pragma unroll
            for (int jc = 0; jc < 2; jc++){
                int jl = jl0 + jc, j = n0 + jl, c = rs*2 + jc;
                float xr = 0.f, xz = 0.f, xn = 0.f;
                #pragma unroll
                for (int cc = 0; cc < Iq; cc++){
                    float xv = Xs[(m - m0)*Iq + cc];
                    xr += xv*Wis[jl*Iq + cc];
                    xz += xv*Wis[(32+jl)*Iq + cc];
                    xn += xv*Wis[(64+jl)*Iq + cc];
                }
                float gr, gz, gn;
                if (DEC){
                    gr = __ldcg(&g_giz[m*G3 + j]);
                    gz = __ldcg(&g_giz[m*G3 + Hq + j]);
                    gn = __ldcg(&g_giz[m*G3 + 2*Hq + j]);
                } else {
                    gr = __ldg(&bih[j]); gz = __ldg(&bih[Hq+j]); gn = __ldg(&bih[2*Hq+j]);
                }
                float rr = sgm(ar[ti][c] + xr + gr + __ldg(&bhh[j]));
                float zz = sgm(az[ti][c] + xz + gz + __ldg(&bhh[Hq+j]));
                float nn = tanhf(xn + gn + rr*(an[ti][c] + __ldg(&bhh[2*Hq+j])));
                float ho = __ldcg(&hold[m*Hq + j]);
                hv[jc] = (1.f - zz)*nn + zz*ho;
                hnew[m*Hq + j] = hv[jc];
            }
            int fi = AFI(par^1, ch, kkj, mtg, l);
            ((unsigned*)&g_Afh[fi])[sl0+rs] = pkbf(hv[0], hv[1]);
            ((unsigned*)&g_Afl[fi])[sl0+rs] = pkbf(bres(hv[0]), bres(hv[1]));
        }
    }
}

__global__ void __launch_bounds__(NTHR, 1) vae_kernel(
    const float* __restrict__ x, const float* __restrict__ noise,
    const float* __restrict__ Wih_f, const float* __restrict__ Whh_f,
    const float* __restrict__ bih_f, const float* __restrict__ bhh_f,
    const float* __restrict__ Wih_b, const float* __restrict__ Whh_b,
    const float* __restrict__ bih_b, const float* __restrict__ bhh_b,
    const float* __restrict__ Wmu,  const float* __restrict__ bmu,
    const float* __restrict__ Wvar, const float* __restrict__ bvar,
    const float* __restrict__ Winit,const float* __restrict__ binit,
    const float* __restrict__ Wout, const float* __restrict__ bout,
    const float* __restrict__ Wcih, const float* __restrict__ Wchh,
    const float* __restrict__ bcih, const float* __restrict__ bchh,
    float* __restrict__ out)
{
    extern __shared__ char smc[];
    unsigned smu;
    { unsigned long long t; asm("cvta.to.shared.u64 %0, %1;":"=l"(t):"l"(smc)); smu = (unsigned)t; }
    const int blk = blockIdx.x, tid = threadIdx.x;
    const int lane = tid & 31;
    const int gt = blk*NTHR + tid, gwp = blk*16 + (tid>>5);

    for (int i = gt; i < Bq*Hq; i += NBLK*NTHR){ g_hf[0][i] = 0.f; g_hb[0][i] = 0.f; }
    for (int i = gt; i < 2*64*16*32; i += NBLK*NTHR){
        g_Afh[i] = make_uint4(0,0,0,0); g_Afl[i] = make_uint4(0,0,0,0);
    }
    for (long i = gt; i < (long)3*64*3*128*32; i += NBLK*NTHR){
        int li = (int)(i & 31); long r = i >> 5;
        int ng = (int)(r & 127); r >>= 7;
        int g = (int)(r % 3); r /= 3;
        int kg = (int)(r & 63); int ch = (int)(r >> 6);
        int n = ng*8 + (li>>2), k = kg*16 + 2*(li&3);
        const float* W = (ch==0) ? Whh_f : (ch==1 ? Whh_b : Wchh);
        const float* p = &W[(g*Hq + n)*Hq + k];
        float a0=__ldg(p), a1=__ldg(p+1), a2=__ldg(p+8), a3=__ldg(p+9);
        g_Wfr[i] = make_uint4(pkbf(a0,a1), pkbf(a2,a3),
                              pkbf(bres(a0),bres(a1)), pkbf(bres(a2),bres(a3)));
    }
    gbar();

    const int edir = blk >> 6, erem = blk & 63;
    const int em0 = (erem >> 5)*128, en0 = (erem & 31)*32;
    for (int t = 0; t < Tq; t++){
        int par = t & 1;
        if (edir == 0)
            gtile<8,0>(smc, smu, par, 0, x, t, Wih_f, Iq, bih_f, bhh_f,
                       g_hf[par], g_hf[par^1], em0, en0);
        else
            gtile<8,0>(smc, smu, par, 1, x, Tq-1-t, Wih_b, Iq, bih_b, bhh_b,
                       g_hb[par], g_hb[par^1], em0, en0);
        gbar();
    }

    for (int it = gwp; it < Bq*Zq; it += NWARP){
        int m = it >> 7, zi = it & 127;
        const float* hf = &g_hf[0][m*Hq];
        const float* hb = &g_hb[0][m*Hq];
        const float* wm = &Wmu[zi*2*Hq];
        const float* wv = &Wvar[zi*2*Hq];
        float am = 0.f, av = 0.f;
        for (int k = lane; k < Hq; k += 32){
            float h1 = __ldcg(&hf[k]); am += h1*__ldg(&wm[k]);    av += h1*__ldg(&wv[k]);
            float h2 = __ldcg(&hb[k]); am += h2*__ldg(&wm[Hq+k]); av += h2*__ldg(&wv[Hq+k]);
        }
        am = wred(am); av = wred(av);
        if (lane == 0){
            float mean = am + __ldg(&bmu[zi]);
            float sd = expf(0.5f*(av + __ldg(&bvar[zi])));
            out[OFF_MEAN + m*Zq + zi] = mean;
            out[OFF_STD  + m*Zq + zi] = sd;
            g_z[m*Zq + zi] = mean + sd*__ldg(&noise[m*Zq + zi]);
        }
    }
    gbar();

    for (int it = gwp; it < Bq*G3; it += NWARP){
        int m = it / G3, gc = it - m*G3;
        const float* zr = &g_z[m*Zq];
        const float* wr = &Wcih[gc*(Iq + Zq) + Iq];
        float acc = 0.f;
        for (int k = lane; k < Zq; k += 32) acc += __ldcg(&zr[k])*__ldg(&wr[k]);
        acc = wred(acc);
        if (lane == 0) g_giz[m*G3 + gc] = acc + __ldg(&bcih[gc]);
    }
    for (int it = gwp; it < Bq*Hq; it += NWARP){
        int m = it >> 10, jj = it & 1023;
        const float* zr = &g_z[m*Zq];
        const float* wr = &Winit[jj*Zq];
        float acc = 0.f;
        for (int k = lane; k < Zq; k += 32) acc += __ldcg(&zr[k])*__ldg(&wr[k]);
        acc = wred(acc);
        if (lane == 0) g_hd[0][m*Hq + jj] = tanhf(acc + __ldg(&binit[jj]));
    }
    gbar();

    for (int i = gt; i < 64*16*32; i += NBLK*NTHR){
        int li = i & 31, mg = (i>>5) & 15, kg = i >> 9;
        int r0 = mg*16 + (li>>2), k = kg*16 + 2*(li&3);
        const float* h2 = g_hd[0];
        float a0=__ldcg(&h2[r0*Hq+k]),     a1=__ldcg(&h2[r0*Hq+k+1]);
        float b0=__ldcg(&h2[(r0+8)*Hq+k]), b1=__ldcg(&h2[(r0+8)*Hq+k+1]);
        float c0=__ldcg(&h2[r0*Hq+k+8]),   c1=__ldcg(&h2[r0*Hq+k+9]);
        float d0=__ldcg(&h2[(r0+8)*Hq+k+8]),d1=__ldcg(&h2[(r0+8)*Hq+k+9]);
        int fi = AFI(0,2,kg,mg,li);
        g_Afh[fi] = make_uint4(pkbf(a0,a1), pkbf(b0,b1), pkbf(c0,c1), pkbf(d0,d1));
        g_Afl[fi] = make_uint4(pkbf(bres(a0),bres(a1)), pkbf(bres(b0),bres(b1)),
                               pkbf(bres(c0),bres(c1)), pkbf(bres(d0),bres(d1)));
    }
    gbar();

    const int dm0 = (blk >> 5)*64, dn0 = (blk & 31)*32;
    for (int t = 0; t < Tq; t++){
        int par = t & 1;
        if (t > 0){
            const float* hbuf = g_hd[par];
            for (int it = gwp; it < Bq*Iq; it += NWARP){
                int m = it / Iq, i = it - m*Iq;
                const float* h = &hbuf[m*Hq];
                const float* ww = &Wout[i*Hq];
                float acc = 0.f;
                for (int k = lane; k < Hq; k += 32) acc += __ldcg(&h[k])*__ldg(&ww[k]);
                acc = wred(acc);
                if (lane == 0)
                    out[m*(Tq*Iq) + (t-1)*Iq + i] = sgm(acc + __ldg(&bout[i]));
            }
        }
        gtile<4,1>(smc, smu, par, 2, x, t, Wcih, Iq + Zq, bcih, bchh,
                   g_hd[par], g_hd[par^1], dm0, dn0);
        gbar();
    }
    {
        const float* hbuf = g_hd[0];
        for (int it = gwp; it < Bq*Iq; it += NWARP){
            int m = it / Iq, i = it - m*Iq;
            const float* h = &hbuf[m*Hq];
            const float* ww = &Wout[i*Hq];
            float acc = 0.f;
            for (int k = lane; k < Hq; k += 32) acc += __ldcg(&h[k])*__ldg(&ww[k]);
            acc = wred(acc);
            if (lane == 0)
                out[m*(Tq*Iq) + (Tq-1)*Iq + i] = sgm(acc + __ldg(&bout[i]));
        }
    }
}

extern "C" void kernel_launch(void* const* d_in, const int* in_sizes, int n_in,
                              void* d_out, int out_size)
{
    cudaFuncSetAttribute(vae_kernel, cudaFuncAttributeMaxDynamicSharedMemorySize, SMTOT);
    vae_kernel<<<NBLK, NTHR, SMTOT>>>(
        (const float*)d_in[0],  (const float*)d_in[1],
        (const float*)d_in[2],  (const float*)d_in[3],
        (const float*)d_in[4],  (const float*)d_in[5],
        (const float*)d_in[6],  (const float*)d_in[7],
        (const float*)d_in[8],  (const float*)d_in[9],
        (const float*)d_in[10], (const float*)d_in[11],
        (const float*)d_in[12], (const float*)d_in[13],
        (const float*)d_in[14], (const float*)d_in[15],
        (const float*)d_in[16], (const float*)d_in[17],
        (const float*)d_in[18], (const float*)d_in[19],
        (const float*)d_in[20], (const float*)d_in[21],
        (float*)d_out);
}